// round 14
// baseline (speedup 1.0000x reference)
#include <cuda_runtime.h>

typedef unsigned long long ull;

#define TT       30
#define BB       1048576
#define THREADS  64
#define M        3
#define EPB      (THREADS * M)            // 192 elements per CTA (consecutive)
#define NBLK     ((BB + EPB - 1) / EPB)   // 5462 (last CTA partial: 64 valid)
#define F4_PER_BLK (EPB * TT / 4)         // 1440 float4 staged per CTA
#define TOTF4    (BB * TT / 4)            // 7864320 float4 in x / out

// ALL weights in constant memory (LDC port only; ~56% at 18.5 warp-streams/SMSP).
__constant__ __align__(16) float cW1[TT * 2 * 20];  // 1200 floats
__constant__ __align__(16) float cB1[TT * 20];      // 600
__constant__ __align__(16) float cW2[TT * 20];      // 600
__constant__ __align__(16) float cB2[TT];           // 30

// ---------------- packed f32x2 helpers ----------------
__device__ __forceinline__ ull pk(float lo, float hi) {
    ull r; asm("mov.b64 %0, {%1,%2};" : "=l"(r) : "f"(lo), "f"(hi)); return r;
}
__device__ __forceinline__ void upk(float& lo, float& hi, ull v) {
    asm("mov.b64 {%0,%1}, %2;" : "=f"(lo), "=f"(hi) : "l"(v));
}
__device__ __forceinline__ ull fma2(ull a, ull b, ull c) {
    ull d; asm("fma.rn.f32x2 %0, %1, %2, %3;" : "=l"(d) : "l"(a), "l"(b), "l"(c)); return d;
}
__device__ __forceinline__ ull add2(ull a, ull b) {
    ull d; asm("add.rn.f32x2 %0, %1, %2;" : "=l"(d) : "l"(a), "l"(b)); return d;
}
__device__ __forceinline__ ull relu2(ull v) {
    float a, b; upk(a, b, v);
    return pk(fmaxf(a, 0.0f), fmaxf(b, 0.0f));
}
// tanh(z) = 1 - 2/(exp(2z)+1) via MUFU.EX2 + MUFU.RCP (~1e-6 rel err)
__device__ __forceinline__ float fast_tanh(float z) {
    float e; asm("ex2.approx.f32 %0, %1;" : "=f"(e) : "f"(z * 2.8853900817779268f));
    float r; asm("rcp.approx.f32 %0, %1;" : "=f"(r) : "f"(e + 1.0f));
    return fmaf(-2.0f, r, 1.0f);
}

#define SMEM_FLOATS (EPB * TT)   // 5760 floats = 23040 bytes -> 9 CTAs/SM

__global__ __launch_bounds__(THREADS, 9)
void rnn_kernel(const float* __restrict__ gx,
                float* __restrict__ gout)
{
    extern __shared__ float sIO[];

    const int tid   = threadIdx.x;
    const int base4 = blockIdx.x * F4_PER_BLK;   // float4 base in gx/gout

    // ---- stage x: linear, perfectly coalesced float4 (guarded for tail CTA) ----
    {
        float4*       d = (float4*)sIO;
        const float4* s = (const float4*)gx;
        for (int i = tid; i < F4_PER_BLK; i += THREADS)
            if (base4 + i < TOTF4) d[i] = s[base4 + i];
    }
    __syncthreads();

    // This thread's 3 elements: local indices tid, tid+64, tid+128 (consecutive block)
    float* io[M];
    #pragma unroll
    for (int k = 0; k < M; ++k) io[k] = sIO + (tid + k * THREADS) * TT;

    const ull* w1u = (const ull*)cW1;   // per t: 20 ulls (10 row0 pairs, 10 row1 pairs)
    const ull* b1u = (const ull*)cB1;   // per t: 10 ulls
    const ull* w2u = (const ull*)cW2;   // per t: 10 ulls

    float o[M];
    #pragma unroll
    for (int m = 0; m < M; ++m) o[m] = 0.0f;

    #pragma unroll 2
    for (int t = 0; t < TT; ++t) {
        const ulonglong2* w1t = (const ulonglong2*)(w1u + t * 20);  // LDC.128
        const ulonglong2* b1t = (const ulonglong2*)(b1u + t * 10);  // LDC.128
        const ulonglong2* w2t = (const ulonglong2*)(w2u + t * 10);  // LDC.128
        const float bt2 = cB2[t];

        ull xx[M], oo[M], accA[M], accB[M];
        #pragma unroll
        for (int m = 0; m < M; ++m) {
            float x = io[m][t];
            xx[m]   = pk(x, x);
            oo[m]   = pk(o[m], o[m]);
            accA[m] = pk(bt2, 0.0f);
            accB[m] = pk(0.0f, 0.0f);
        }

        #pragma unroll
        for (int q = 0; q < 5; ++q) {
            ulonglong2 wa = w1t[q];       // W1 row0, hidden 4q..4q+3
            ulonglong2 wb = w1t[5 + q];   // W1 row1
            ulonglong2 bb = b1t[q];       // b1
            ulonglong2 w2 = w2t[q];       // W2

            #pragma unroll
            for (int m = 0; m < M; ++m) {
                ull hA = fma2(xx[m], wa.x, fma2(oo[m], wb.x, bb.x));
                ull hB = fma2(xx[m], wa.y, fma2(oo[m], wb.y, bb.y));
                accA[m] = fma2(relu2(hA), w2.x, accA[m]);
                accB[m] = fma2(relu2(hB), w2.y, accB[m]);
            }
        }

        #pragma unroll
        for (int m = 0; m < M; ++m) {
            float a, b;
            upk(a, b, add2(accA[m], accB[m]));
            o[m] = fast_tanh(a + b);
            io[m][t] = o[m];            // output overwrites consumed x slot
        }
    }

    __syncthreads();

    // ---- writeback: linear coalesced float4 (guarded for tail CTA) ----
    {
        const float4* s = (const float4*)sIO;
        float4*       d = (float4*)gout;
        for (int i = tid; i < F4_PER_BLK; i += THREADS)
            if (base4 + i < TOTF4) d[base4 + i] = s[i];
    }
}

extern "C" void kernel_launch(void* const* d_in, const int* in_sizes, int n_in,
                              void* d_out, int out_size)
{
    const float* x = (const float*)d_in[0];

    // Populate constant bank (graph-capturable D2D memcpys, no allocation).
    void *pW1, *pB1, *pW2, *pB2;
    cudaGetSymbolAddress(&pW1, cW1);
    cudaGetSymbolAddress(&pB1, cB1);
    cudaGetSymbolAddress(&pW2, cW2);
    cudaGetSymbolAddress(&pB2, cB2);
    cudaMemcpyAsync(pW1, d_in[1], sizeof(float) * TT * 2 * 20, cudaMemcpyDeviceToDevice);
    cudaMemcpyAsync(pB1, d_in[2], sizeof(float) * TT * 20,     cudaMemcpyDeviceToDevice);
    cudaMemcpyAsync(pW2, d_in[3], sizeof(float) * TT * 20,     cudaMemcpyDeviceToDevice);
    cudaMemcpyAsync(pB2, d_in[4], sizeof(float) * TT,          cudaMemcpyDeviceToDevice);

    const int smem_bytes = SMEM_FLOATS * (int)sizeof(float);   // 23040
    cudaFuncSetAttribute(rnn_kernel, cudaFuncAttributeMaxDynamicSharedMemorySize, smem_bytes);

    rnn_kernel<<<NBLK, THREADS, smem_bytes>>>(x, (float*)d_out);
}